// round 13
// baseline (speedup 1.0000x reference)
#include <cuda_runtime.h>

// Problem constants
#define B_    4
#define C_    256
#define H_    64
#define W_    64
#define HW_   4096
#define NUM_  9
#define NC_   27   // candidates per pixel after propagate
#define K_    9    // top-k kept

// Scratch (no allocations allowed — use __device__ globals)
__device__ float g_leftT [(size_t)B_ * HW_ * C_];   // [b][pixel][c]
__device__ float g_rightT[(size_t)B_ * HW_ * C_];   // [b*HW+p][c]
__device__ int   g_inds1 [B_ * NUM_ * HW_];         // pass-1 top-9 inds, [b][k][hw]

// ---------------------------------------------------------------------------
// exp(d) for d <= 0: IEEE-754 float32 bit pattern of the RN result.
// Subnormal results produced exactly; caller flushes them (XLA-GPU FTZ).
// Immune to -ftz / fast-math (integer bit assembly, normal-range float ops).
// ---------------------------------------------------------------------------
__device__ __forceinline__ unsigned exp_f32_bits(float d)
{
    if (d < -106.0f) return 0u;
    float t  = d * 1.4426950408889634f;            // log2(e)
    float fi = floorf(t);
    float f  = t - fi;                             // [0, 1)
    int   i  = (int)fi;
    float p2 = fmaf(f, 1.0178086e-07f, 1.3215487e-06f);
    p2 = fmaf(f, p2, 1.5252734e-05f);
    p2 = fmaf(f, p2, 1.5403530e-04f);
    p2 = fmaf(f, p2, 1.3333558e-03f);
    p2 = fmaf(f, p2, 9.6181291e-03f);
    p2 = fmaf(f, p2, 5.5504109e-02f);
    p2 = fmaf(f, p2, 2.4022651e-01f);
    p2 = fmaf(f, p2, 6.9314718e-01f);
    p2 = fmaf(f, p2, 1.0f);
    if (i >= -126) {
        unsigned S = __float2uint_rn(p2 * 8388608.0f);
        if (S >= (1u << 24)) { S >>= 1; i += 1; }
        return (((unsigned)(i + 127)) << 23) + (S - (1u << 23));
    } else {
        float v = ldexpf(p2, i + 149);
        return __float2uint_rn(v);                 // subnormal bits
    }
}

// ---------------------------------------------------------------------------
// Fused transpose: z = 0..3 -> left batch z, z = 4..7 -> right batch z-4.
// (256 x 4096) -> (4096 x 256), tiled 32x32 in smem.
// ---------------------------------------------------------------------------
__global__ void transpose_kernel(const float* __restrict__ left,
                                 const float* __restrict__ right)
{
    __shared__ float tile[32][33];
    int bx = blockIdx.x, by = blockIdx.y, bz = blockIdx.z;
    int tx = threadIdx.x, ty = threadIdx.y;  // (32, 8)

    bool is_right = bz >= 4;
    int  bb       = is_right ? bz - 4 : bz;
    const float* ip = is_right ? (right + (long)bb * HW_)
                               : (left  + (long)bb * C_ * HW_);
    long rstride   = is_right ? (long)B_ * HW_ : (long)HW_;
    float* op      = (is_right ? g_rightT : g_leftT) + (long)bb * HW_ * C_;

    int c = bx * 32 + tx;
#pragma unroll
    for (int i = 0; i < 4; i++) {
        int r = by * 32 + ty + i * 8;
        tile[ty + i * 8][tx] = ip[(long)r * rstride + c];
    }
    __syncthreads();
#pragma unroll
    for (int i = 0; i < 4; i++) {
        int p = bx * 32 + ty + i * 8;
        op[(long)p * C_ + by * 32 + tx] = tile[tx][ty + i * 8];
    }
}

// ---------------------------------------------------------------------------
// Fused evaluate: TWO warps per pixel, split by channel halves (warp h owns
// channels h*128..h*128+127; one LDG.128 per lane per candidate). Halves are
// combined through a small smem exchange; h=0 warps run the softmax/top-k
// tail using redux/ballot (vote+ALU pipes) to unload the LSU.
// PASS==1: horizontal propagate from raw float offsets, write top-9 inds.
// PASS==2: vertical propagate from g_inds1, write ox / oy / corr to output.
// ---------------------------------------------------------------------------
template <int PASS>
__global__ void __launch_bounds__(256, 5)
eval_kernel(const float* __restrict__ offx,
            const float* __restrict__ offy,
            float* __restrict__ out)
{
    const unsigned FULL = 0xffffffffu;
    int t    = threadIdx.x;
    int warp = t >> 5;
    int lane = t & 31;
    int pixw = warp >> 1;               // pixel-in-block 0..3
    int h    = warp & 1;                // channel half
    int gw   = blockIdx.x * 4 + pixw;   // global pixel
    int b  = gw >> 12;
    int hw = gw & (HW_ - 1);
    int y = hw >> 6, x = hw & 63;

    __shared__ float s_half[4][2][32];

    // --- candidate indices: lane n < 27 owns candidate n (both warps) ---
    // n = g*9 + j : g=0 left/up neighbor, g=1 self, g=2 right/down neighbor.
    // Out-of-image neighbor => padded offset 0 => candidate = self pixel.
    int cand = hw;
    if (lane < NC_) {
        int g = (lane >= 18) ? 2 : ((lane >= 9) ? 1 : 0);
        int j = lane - g * 9;
        if (PASS == 1) {
            int sx = x + g - 1;
            if (sx >= 0 && sx < W_) {
                int o = ((b * NUM_ + j) * H_ + y) * W_ + sx;
                float ox = offx[o];
                float oy = offy[o];
                float px = fminf(fmaxf((float)x + ox, 0.f), (float)(W_ - 1));
                float py = fminf(fmaxf((float)y + oy, 0.f), (float)(H_ - 1));
                cand = (int)(py * (float)W_ + px);
            }
        } else {
            int sy = y + g - 1;
            if (sy >= 0 && sy < H_) {
                int ip = g_inds1[(b * NUM_ + j) * HW_ + sy * W_ + x];
                int ix = ip & 63;
                int iy = ip >> 6;
                int py = min(max(iy + (y - sy), 0), H_ - 1);
                cand = py * W_ + ix;
            }
        }
    }

    // --- left feature vector: 4 channels per lane (this warp's half) ---
    const float4 L = *reinterpret_cast<const float4*>(
        g_leftT + (size_t)(b * HW_ + hw) * C_ + h * 128 + lane * 4);

    // --- 27 gathered per-lane partial dots (4 channels each) ---
    const float* rbase = g_rightT + (size_t)b * HW_ * C_ + h * 128 + lane * 4;
    float acc[NC_];
#pragma unroll
    for (int n = 0; n < NC_; n++) {
        int ind = __shfl_sync(FULL, cand, n);
        float4 r = *reinterpret_cast<const float4*>(rbase + (size_t)ind * C_);
        float s = L.x * r.x;
        s = fmaf(L.y, r.y, s);
        s = fmaf(L.z, r.z, s);
        s = fmaf(L.w, r.w, s);
        acc[n] = s;
    }

    // --- recursive vector-halving reduction: 31 shuffles + 31 adds.
    //     Afterwards lane n holds this half's 128-channel dot of cand n. ---
#pragma unroll
    for (int m = 16; m >= 1; m >>= 1) {
        bool hi = (lane & m) != 0;
#pragma unroll
        for (int i = 0; i < m; i++) {
            float hiv  = (i + m < NC_) ? acc[i + m] : 0.f;
            float send = hi ? acc[i] : hiv;
            float recv = __shfl_xor_sync(FULL, send, m);
            float keep = hi ? hiv : acc[i];
            acc[i] = keep + recv;
        }
    }

    // --- combine halves through smem; only h=0 warps run the tail ---
    s_half[pixw][h][lane] = acc[0];
    __syncthreads();

    if (h == 0) {
        float dot  = s_half[pixw][0][lane] + s_half[pixw][1][lane];
        float cost = (lane < NC_) ? __fdiv_rn(dot, 0.01f) : -3.402823466e38f;

        // --- warp max via redux on order-mapped bits (vote/ALU pipe) ---
        unsigned cb = __float_as_uint(cost);
        unsigned ob = cb ^ (unsigned)(((int)cb >> 31) | 0x80000000);
        unsigned om = __reduce_max_sync(FULL, ob);
        float mx = __uint_as_float((om & 0x80000000u) ? (om ^ 0x80000000u) : ~om);

        // --- one exp per lane, flush subnormal (XLA-GPU FTZ emulation) ---
        unsigned e = (lane < NC_) ? exp_f32_bits(cost - mx) : 0u;
        if (e < 0x00800000u) e = 0u;
        float ef = __uint_as_float(e);

        // --- warp sum (butterfly: identical result on all lanes) ---
        float ps = ef;
#pragma unroll
        for (int off = 16; off > 0; off >>= 1)
            ps += __shfl_xor_sync(FULL, ps, off);

        unsigned p = __float_as_uint(__fdiv_rn(ef, ps));
        if (p < 0x00800000u) p = 0u;               // flush subnormal prob

        // --- top-9 by 9 selection rounds: redux.max + ballot per round.
        //     Equal prob bits -> lowest lane wins == jax.lax.top_k stable
        //     order (prob bits non-negative: uint order == float order). ---
        bool taken = false;
#pragma unroll 1
        for (int k = 0; k < K_; k++) {
            unsigned kk = (taken || lane >= NC_) ? 0u : p;
            unsigned mk = __reduce_max_sync(FULL, kk);
            unsigned cm = __ballot_sync(FULL, (lane < NC_) && !taken && (kk == mk));
            int winner = __ffs(cm) - 1;
            if (lane == winner) {
                taken = true;
                int o = (b * NUM_ + k) * HW_ + hw;
                if (PASS == 1) {
                    g_inds1[o] = cand;
                } else {
                    out[o]                       = (float)((cand & 63) - x);  // ox
                    out[B_ * NUM_ * HW_ + o]     = (float)((cand >> 6) - y);  // oy
                    out[2 * B_ * NUM_ * HW_ + o] = __uint_as_float(p);        // corr
                }
            }
        }
    }
}

// ---------------------------------------------------------------------------
extern "C" void kernel_launch(void* const* d_in, const int* in_sizes, int n_in,
                              void* d_out, int out_size)
{
    const float* left  = (const float*)d_in[0];  // (B, C, HW)
    const float* right = (const float*)d_in[1];  // (C, B*HW)
    const float* offx  = (const float*)d_in[2];  // (B, 9, H, W)
    const float* offy  = (const float*)d_in[3];  // (B, 9, H, W)
    float* out = (float*)d_out;                  // ox | oy | corr concatenated

    dim3 tb(32, 8);
    dim3 tg(HW_ / 32, C_ / 32, 2 * B_);          // z: 0..3 left, 4..7 right
    transpose_kernel<<<tg, tb>>>(left, right);

    int nblocks = (B_ * HW_) / 4;   // 4 pixels x 2 warps per 256-thread block
    eval_kernel<1><<<nblocks, 256>>>(offx, offy, nullptr);
    eval_kernel<2><<<nblocks, 256>>>(nullptr, nullptr, out);
}

// round 14
// speedup vs baseline: 1.1015x; 1.1015x over previous
#include <cuda_runtime.h>

// Problem constants
#define B_    4
#define C_    256
#define H_    64
#define W_    64
#define HW_   4096
#define NUM_  9
#define NC_   27   // candidates per pixel after propagate
#define K_    9    // top-k kept

// Scratch (no allocations allowed — use __device__ globals)
__device__ float g_leftT [(size_t)B_ * HW_ * C_];   // [b][pixel][c]
__device__ float g_rightT[(size_t)B_ * HW_ * C_];   // [b*HW+p][c]
__device__ int   g_inds1 [B_ * NUM_ * HW_];         // pass-1 top-9 inds, [b][k][hw]

// ---------------------------------------------------------------------------
// exp(d) for d <= 0: IEEE-754 float32 bit pattern of the RN result.
// Subnormal results produced exactly; caller flushes them (XLA-GPU FTZ).
// Immune to -ftz / fast-math (integer bit assembly, normal-range float ops).
// ---------------------------------------------------------------------------
__device__ __forceinline__ unsigned exp_f32_bits(float d)
{
    if (d < -106.0f) return 0u;
    float t  = d * 1.4426950408889634f;            // log2(e)
    float fi = floorf(t);
    float f  = t - fi;                             // [0, 1)
    int   i  = (int)fi;
    float p2 = fmaf(f, 1.0178086e-07f, 1.3215487e-06f);
    p2 = fmaf(f, p2, 1.5252734e-05f);
    p2 = fmaf(f, p2, 1.5403530e-04f);
    p2 = fmaf(f, p2, 1.3333558e-03f);
    p2 = fmaf(f, p2, 9.6181291e-03f);
    p2 = fmaf(f, p2, 5.5504109e-02f);
    p2 = fmaf(f, p2, 2.4022651e-01f);
    p2 = fmaf(f, p2, 6.9314718e-01f);
    p2 = fmaf(f, p2, 1.0f);
    if (i >= -126) {
        unsigned S = __float2uint_rn(p2 * 8388608.0f);
        if (S >= (1u << 24)) { S >>= 1; i += 1; }
        return (((unsigned)(i + 127)) << 23) + (S - (1u << 23));
    } else {
        float v = ldexpf(p2, i + 149);
        return __float2uint_rn(v);                 // subnormal bits
    }
}

// ---------------------------------------------------------------------------
// Fused vectorized transpose: z = 0..3 -> left batch z, z = 4..7 -> right
// batch z-4. Tiles of 32 rows x 128 cols, float4 global loads AND stores,
// XOR-swizzled float4 smem tile (conflict-free both phases).
//   element (r, c) of the tile lives at tile4[r*32 + ((c>>2) ^ (r>>2))],
//   component c&3.
// ---------------------------------------------------------------------------
__global__ void __launch_bounds__(256) transpose_kernel(
    const float* __restrict__ left, const float* __restrict__ right)
{
    __shared__ float4 tile4[32 * 32];                 // 16 KB
    const float* tilef = reinterpret_cast<const float*>(tile4);
    int tx = threadIdx.x, ty = threadIdx.y;           // (32, 8)
    int bx = blockIdx.x, by = blockIdx.y, bz = blockIdx.z;

    bool is_right = bz >= 4;
    int  bb       = is_right ? bz - 4 : bz;
    const float* ip = is_right ? (right + (long)bb * HW_)
                               : (left  + (long)bb * C_ * HW_);
    long rstride   = is_right ? (long)B_ * HW_ : (long)HW_;
    float* op      = (is_right ? g_rightT : g_leftT) + (long)bb * HW_ * C_;

    // load: 32 rows (C-dim) x 128 cols (HW-dim); one float4 per thread per iter
#pragma unroll
    for (int i = 0; i < 4; i++) {
        int rr  = ty + i * 8;
        int r_g = by * 32 + rr;
        float4 v = *reinterpret_cast<const float4*>(
            ip + (long)r_g * rstride + bx * 128 + tx * 4);
        tile4[rr * 32 + (tx ^ (rr >> 2))] = v;        // swizzled, conflict-free
    }
    __syncthreads();

    // store: 1024 output float4s (128 out-rows x 8 float4s); 4 per thread
    int tid = ty * 32 + tx;
#pragma unroll
    for (int it = 0; it < 4; it++) {
        int j    = it * 256 + tid;
        int cc   = j >> 3;                 // out row within tile (HW-dim) 0..127
        int rrb  = (j & 7) * 4;            // out col base (C-dim)
        int q    = cc >> 2;
        float4 v;
        v.x = tilef[(rrb + 0) * 128 + ((q ^ ((rrb + 0) >> 2)) << 2) + (cc & 3)];
        v.y = tilef[(rrb + 1) * 128 + ((q ^ ((rrb + 1) >> 2)) << 2) + (cc & 3)];
        v.z = tilef[(rrb + 2) * 128 + ((q ^ ((rrb + 2) >> 2)) << 2) + (cc & 3)];
        v.w = tilef[(rrb + 3) * 128 + ((q ^ ((rrb + 3) >> 2)) << 2) + (cc & 3)];
        *reinterpret_cast<float4*>(
            op + (long)(bx * 128 + cc) * C_ + by * 32 + rrb) = v;
    }
}

// ---------------------------------------------------------------------------
// Fused evaluate (R12 form): TWO warps per pixel, split by channel halves
// (warp h owns channels h*128..h*128+127; one LDG.128 per lane per cand).
// Halves combine through a small smem exchange; h=0 warps run the tail.
// PASS==1: horizontal propagate from raw float offsets, write top-9 inds.
// PASS==2: vertical propagate from g_inds1, write ox / oy / corr to output.
// ---------------------------------------------------------------------------
template <int PASS>
__global__ void __launch_bounds__(256, 5)
eval_kernel(const float* __restrict__ offx,
            const float* __restrict__ offy,
            float* __restrict__ out)
{
    const unsigned FULL = 0xffffffffu;
    int t    = threadIdx.x;
    int warp = t >> 5;
    int lane = t & 31;
    int pixw = warp >> 1;               // pixel-in-block 0..3
    int h    = warp & 1;                // channel half
    int gw   = blockIdx.x * 4 + pixw;   // global pixel
    int b  = gw >> 12;
    int hw = gw & (HW_ - 1);
    int y = hw >> 6, x = hw & 63;

    __shared__ float s_half[4][2][32];

    // --- candidate indices: lane n < 27 owns candidate n (both warps) ---
    // n = g*9 + j : g=0 left/up neighbor, g=1 self, g=2 right/down neighbor.
    // Out-of-image neighbor => padded offset 0 => candidate = self pixel.
    int cand = hw;
    if (lane < NC_) {
        int g = (lane >= 18) ? 2 : ((lane >= 9) ? 1 : 0);
        int j = lane - g * 9;
        if (PASS == 1) {
            int sx = x + g - 1;
            if (sx >= 0 && sx < W_) {
                int o = ((b * NUM_ + j) * H_ + y) * W_ + sx;
                float ox = offx[o];
                float oy = offy[o];
                float px = fminf(fmaxf((float)x + ox, 0.f), (float)(W_ - 1));
                float py = fminf(fmaxf((float)y + oy, 0.f), (float)(H_ - 1));
                cand = (int)(py * (float)W_ + px);
            }
        } else {
            int sy = y + g - 1;
            if (sy >= 0 && sy < H_) {
                int ip = g_inds1[(b * NUM_ + j) * HW_ + sy * W_ + x];
                int ix = ip & 63;
                int iy = ip >> 6;
                int py = min(max(iy + (y - sy), 0), H_ - 1);
                cand = py * W_ + ix;
            }
        }
    }

    // --- left feature vector: 4 channels per lane (this warp's half) ---
    const float4 L = *reinterpret_cast<const float4*>(
        g_leftT + (size_t)(b * HW_ + hw) * C_ + h * 128 + lane * 4);

    // --- 27 gathered per-lane partial dots (4 channels each) ---
    const float* rbase = g_rightT + (size_t)b * HW_ * C_ + h * 128 + lane * 4;
    float acc[NC_];
#pragma unroll
    for (int n = 0; n < NC_; n++) {
        int ind = __shfl_sync(FULL, cand, n);
        float4 r = *reinterpret_cast<const float4*>(rbase + (size_t)ind * C_);
        float s = L.x * r.x;
        s = fmaf(L.y, r.y, s);
        s = fmaf(L.z, r.z, s);
        s = fmaf(L.w, r.w, s);
        acc[n] = s;
    }

    // --- recursive vector-halving reduction: 31 shuffles + 31 adds.
    //     Afterwards lane n holds this half's 128-channel dot of cand n. ---
#pragma unroll
    for (int m = 16; m >= 1; m >>= 1) {
        bool hi = (lane & m) != 0;
#pragma unroll
        for (int i = 0; i < m; i++) {
            float hiv  = (i + m < NC_) ? acc[i + m] : 0.f;
            float send = hi ? acc[i] : hiv;
            float recv = __shfl_xor_sync(FULL, send, m);
            float keep = hi ? hiv : acc[i];
            acc[i] = keep + recv;
        }
    }

    // --- combine halves through smem; only h=0 warps run the tail ---
    s_half[pixw][h][lane] = acc[0];
    __syncthreads();

    if (h == 0) {
        float dot  = s_half[pixw][0][lane] + s_half[pixw][1][lane];
        float cost = (lane < NC_) ? __fdiv_rn(dot, 0.01f) : -3.402823466e38f;

        // --- warp max (bitwise-identical on all lanes) ---
        float mx = cost;
#pragma unroll
        for (int off = 16; off > 0; off >>= 1)
            mx = fmaxf(mx, __shfl_xor_sync(FULL, mx, off));

        // --- one exp per lane, flush subnormal (XLA-GPU FTZ emulation) ---
        unsigned e = (lane < NC_) ? exp_f32_bits(cost - mx) : 0u;
        if (e < 0x00800000u) e = 0u;
        float ef = __uint_as_float(e);

        // --- warp sum (butterfly: identical result on all lanes) ---
        float ps = ef;
#pragma unroll
        for (int off = 16; off > 0; off >>= 1)
            ps += __shfl_xor_sync(FULL, ps, off);

        unsigned p = __float_as_uint(__fdiv_rn(ef, ps));
        if (p < 0x00800000u) p = 0u;               // flush subnormal prob

        // --- rank of own candidate among 27 (descending prob, lowest slot
        //     wins ties == jax.lax.top_k stable order). rank<9 lanes write ---
        int rank = 0;
#pragma unroll
        for (int m2 = 0; m2 < NC_; m2++) {
            unsigned pm = __shfl_sync(FULL, p, m2);
            rank += (int)((pm > p) | ((pm == p) & (m2 < lane)));
        }

        if (lane < NC_ && rank < K_) {
            int o = (b * NUM_ + rank) * HW_ + hw;
            if (PASS == 1) {
                g_inds1[o] = cand;
            } else {
                out[o]                       = (float)((cand & 63) - x);  // ox
                out[B_ * NUM_ * HW_ + o]     = (float)((cand >> 6) - y);  // oy
                out[2 * B_ * NUM_ * HW_ + o] = __uint_as_float(p);        // corr
            }
        }
    }
}

// ---------------------------------------------------------------------------
extern "C" void kernel_launch(void* const* d_in, const int* in_sizes, int n_in,
                              void* d_out, int out_size)
{
    const float* left  = (const float*)d_in[0];  // (B, C, HW)
    const float* right = (const float*)d_in[1];  // (C, B*HW)
    const float* offx  = (const float*)d_in[2];  // (B, 9, H, W)
    const float* offy  = (const float*)d_in[3];  // (B, 9, H, W)
    float* out = (float*)d_out;                  // ox | oy | corr concatenated

    dim3 tb(32, 8);
    dim3 tg(HW_ / 128, C_ / 32, 2 * B_);         // z: 0..3 left, 4..7 right
    transpose_kernel<<<tg, tb>>>(left, right);

    int nblocks = (B_ * HW_) / 4;   // 4 pixels x 2 warps per 256-thread block
    eval_kernel<1><<<nblocks, 256>>>(offx, offy, nullptr);
    eval_kernel<2><<<nblocks, 256>>>(nullptr, nullptr, out);
}